// round 6
// baseline (speedup 1.0000x reference)
#include <cuda_runtime.h>
#include <cuda_bf16.h>
#include <cstdint>
#include <cstddef>

// Problem constants
#define BATCH   16
#define NTOK    577
#define CDIM    768
#define HEADS   12
#define DHEAD   64
#define MROWS   (BATCH * NTOK)          // 9232
#define QKVCOLS (3 * CDIM)              // 2304
#define BHTOT   (BATCH * HEADS)         // 192

// ---------------- scratch (no allocations allowed -> device globals) --------
__device__ float g_qkv[(size_t)MROWS * QKVCOLS];              // (B*N, 3C)
__device__ float g_Q[(size_t)BHTOT * NTOK * DHEAD];           // (B*H, N, D)
__device__ float g_K[(size_t)BHTOT * NTOK * DHEAD];
__device__ float g_V[(size_t)BHTOT * NTOK * DHEAD];
__device__ float g_attn[(size_t)MROWS * CDIM];                // (B*N, C)

// ======================= SGEMM: C = A@B + bias ==============================
// BM=128, BN=128, BK=8, 256 threads, 8x8 microtile.
// Requires: N % 128 == 0, K % 8 == 0 (true for both call sites). M edge guarded.
template <int Nc, int Kc>
__device__ __forceinline__ void sgemm_body(const float* __restrict__ A,
                                           const float* __restrict__ Bm,
                                           const float* __restrict__ bias,
                                           float* __restrict__ Cm, int M) {
    __shared__ float As[8][128];
    __shared__ float Bs[8][128];

    const int tid = threadIdx.x;
    const int block_row = blockIdx.y * 128;
    const int block_col = blockIdx.x * 128;
    const int tr = (tid >> 4) << 3;   // 0..120
    const int tc = (tid & 15) << 3;   // 0..120

    // A-load: 2 threads per row, one float4 each
    const int a_row = tid >> 1;
    const int a_col = (tid & 1) << 2;
    // B-load: 32 float4 per row, 8 rows
    const int b_row = tid >> 5;
    const int b_col = (tid & 31) << 2;

    const float* Ag = A + (size_t)block_row * Kc;
    const float* Bg = Bm + block_col;

    float acc[8][8];
#pragma unroll
    for (int i = 0; i < 8; i++)
#pragma unroll
        for (int j = 0; j < 8; j++) acc[i][j] = 0.f;

    for (int k0 = 0; k0 < Kc; k0 += 8) {
        float4 av = make_float4(0.f, 0.f, 0.f, 0.f);
        if (block_row + a_row < M)
            av = *(const float4*)(Ag + (size_t)a_row * Kc + k0 + a_col);
        As[a_col + 0][a_row] = av.x;
        As[a_col + 1][a_row] = av.y;
        As[a_col + 2][a_row] = av.z;
        As[a_col + 3][a_row] = av.w;

        float4 bv = *(const float4*)(Bg + (size_t)(k0 + b_row) * Nc + b_col);
        *(float4*)&Bs[b_row][b_col] = bv;

        __syncthreads();
#pragma unroll
        for (int kk = 0; kk < 8; kk++) {
            float ar[8], br[8];
            *(float4*)&ar[0] = *(const float4*)&As[kk][tr];
            *(float4*)&ar[4] = *(const float4*)&As[kk][tr + 4];
            *(float4*)&br[0] = *(const float4*)&Bs[kk][tc];
            *(float4*)&br[4] = *(const float4*)&Bs[kk][tc + 4];
#pragma unroll
            for (int i = 0; i < 8; i++)
#pragma unroll
                for (int j = 0; j < 8; j++)
                    acc[i][j] = fmaf(ar[i], br[j], acc[i][j]);
        }
        __syncthreads();
    }

#pragma unroll
    for (int i = 0; i < 8; i++) {
        int r = block_row + tr + i;
        if (r < M) {
#pragma unroll
            for (int j = 0; j < 8; j += 4) {
                int c = block_col + tc + j;
                float4 ov;
                ov.x = acc[i][j + 0] + bias[c + 0];
                ov.y = acc[i][j + 1] + bias[c + 1];
                ov.z = acc[i][j + 2] + bias[c + 2];
                ov.w = acc[i][j + 3] + bias[c + 3];
                *(float4*)(Cm + (size_t)r * Nc + c) = ov;
            }
        }
    }
}

__global__ __launch_bounds__(256) void k_gemm_qkv(const float* __restrict__ x,
                                                  const float* __restrict__ w,
                                                  const float* __restrict__ b) {
    sgemm_body<QKVCOLS, CDIM>(x, w, b, g_qkv, MROWS);
}

__global__ __launch_bounds__(256) void k_gemm_proj(const float* __restrict__ w,
                                                   const float* __restrict__ b,
                                                   float* __restrict__ out) {
    sgemm_body<CDIM, CDIM>(g_attn, w, b, out, MROWS);
}

// =============== RoPE + split (B,N,3,H,D) -> Q/K/V (B*H, N, D) ==============
__global__ __launch_bounds__(256) void k_rope_split(const float* __restrict__ cosb,
                                                    const float* __restrict__ sinb) {
    int idx = blockIdx.x * blockDim.x + threadIdx.x;
    const int total = BATCH * HEADS * NTOK * (DHEAD / 2);
    if (idx >= total) return;

    int d2 = idx & 31;
    int n  = (idx >> 5) % NTOK;
    int h  = (idx / (32 * NTOK)) % HEADS;
    int b  = idx / (32 * NTOK * HEADS);

    size_t base = (size_t)(b * NTOK + n) * QKVCOLS + h * DHEAD + (d2 << 1);
    float2 q = *(const float2*)(g_qkv + base);
    float2 k = *(const float2*)(g_qkv + base + CDIM);
    float2 v = *(const float2*)(g_qkv + base + 2 * CDIM);

    if (n > 0) {
        float c = cosb[(size_t)(n - 1) * 32 + d2];
        float s = sinb[(size_t)(n - 1) * 32 + d2];
        float2 qr, kr;
        qr.x = q.x * c - q.y * s;  qr.y = q.x * s + q.y * c;
        kr.x = k.x * c - k.y * s;  kr.y = k.x * s + k.y * c;
        q = qr; k = kr;
    }

    size_t o = ((size_t)(b * HEADS + h) * NTOK + n) * DHEAD + (d2 << 1);
    *(float2*)(g_Q + o) = q;
    *(float2*)(g_K + o) = k;
    *(float2*)(g_V + o) = v;
}

// ====================== Flash attention, fp32, 64x64 tiles ==================
// grid: x = q-tile (10), y = bh (192). 256 threads (16x16), 4x4 per thread.
// smem = 3 * 16KB = 48KB static (Qs transposed; KP = K transposed+swizzled,
// reused for P row-major; Vs row-major).
__global__ __launch_bounds__(256) void k_attn() {
    __shared__ float Qs[DHEAD][64];   // Qs[d][r]
    __shared__ float KP[64][64];      // Ks[d][c^swz] then Ps[r][c]
    __shared__ float Vs[64][DHEAD];   // Vs[c][d]

    const int tid = threadIdx.x;
    const int ty = tid >> 4;
    const int tx = tid & 15;
    const int bh = blockIdx.y;
    const int q0 = blockIdx.x * 64;

    const float* Qg = g_Q + (size_t)bh * NTOK * DHEAD;
    const float* Kg = g_K + (size_t)bh * NTOK * DHEAD;
    const float* Vg = g_V + (size_t)bh * NTOK * DHEAD;

    // load Q tile, transposed
#pragma unroll
    for (int it = 0; it < 4; it++) {
        int idx = tid + it * 256;
        int r  = idx >> 4;
        int d4 = (idx & 15) << 2;
        float4 v = make_float4(0.f, 0.f, 0.f, 0.f);
        if (q0 + r < NTOK) v = *(const float4*)(Qg + (size_t)(q0 + r) * DHEAD + d4);
        Qs[d4 + 0][r] = v.x;
        Qs[d4 + 1][r] = v.y;
        Qs[d4 + 2][r] = v.z;
        Qs[d4 + 3][r] = v.w;
    }

    float m_i[4], l_i[4], o[4][4];
#pragma unroll
    for (int i = 0; i < 4; i++) {
        m_i[i] = -1e30f;
        l_i[i] = 0.f;
#pragma unroll
        for (int j = 0; j < 4; j++) o[i][j] = 0.f;
    }
    const float scale = 0.125f;  // D^-0.5, D=64

    for (int kt = 0; kt < 10; kt++) {
        const int k0 = kt * 64;

        __syncthreads();  // prior PV done; KP/Vs free (also orders Q stores)

        // load K (transposed + bank swizzle) and V (row-major)
#pragma unroll
        for (int it = 0; it < 4; it++) {
            int idx = tid + it * 256;
            int r  = idx >> 4;
            int d4 = (idx & 15) << 2;
            float4 kv = make_float4(0.f, 0.f, 0.f, 0.f);
            float4 vv = make_float4(0.f, 0.f, 0.f, 0.f);
            if (k0 + r < NTOK) {
                kv = *(const float4*)(Kg + (size_t)(k0 + r) * DHEAD + d4);
                vv = *(const float4*)(Vg + (size_t)(k0 + r) * DHEAD + d4);
            }
            KP[d4 + 0][r ^ ((d4 + 0) & 31)] = kv.x;
            KP[d4 + 1][r ^ ((d4 + 1) & 31)] = kv.y;
            KP[d4 + 2][r ^ ((d4 + 2) & 31)] = kv.z;
            KP[d4 + 3][r ^ ((d4 + 3) & 31)] = kv.w;
            *(float4*)&Vs[r][d4] = vv;
        }
        __syncthreads();

        // S = Q @ K^T
        float s[4][4];
#pragma unroll
        for (int i = 0; i < 4; i++)
#pragma unroll
            for (int j = 0; j < 4; j++) s[i][j] = 0.f;

#pragma unroll
        for (int d = 0; d < 64; d++) {
            float4 a = *(const float4*)&Qs[d][ty << 2];
            const int sw = d & 31;
            float b0 = KP[d][((tx << 2) + 0) ^ sw];
            float b1 = KP[d][((tx << 2) + 1) ^ sw];
            float b2 = KP[d][((tx << 2) + 2) ^ sw];
            float b3 = KP[d][((tx << 2) + 3) ^ sw];
            s[0][0] = fmaf(a.x, b0, s[0][0]); s[0][1] = fmaf(a.x, b1, s[0][1]);
            s[0][2] = fmaf(a.x, b2, s[0][2]); s[0][3] = fmaf(a.x, b3, s[0][3]);
            s[1][0] = fmaf(a.y, b0, s[1][0]); s[1][1] = fmaf(a.y, b1, s[1][1]);
            s[1][2] = fmaf(a.y, b2, s[1][2]); s[1][3] = fmaf(a.y, b3, s[1][3]);
            s[2][0] = fmaf(a.z, b0, s[2][0]); s[2][1] = fmaf(a.z, b1, s[2][1]);
            s[2][2] = fmaf(a.z, b2, s[2][2]); s[2][3] = fmaf(a.z, b3, s[2][3]);
            s[3][0] = fmaf(a.w, b0, s[3][0]); s[3][1] = fmaf(a.w, b1, s[3][1]);
            s[3][2] = fmaf(a.w, b2, s[3][2]); s[3][3] = fmaf(a.w, b3, s[3][3]);
        }

        // online softmax (per query row, reduce across 16 tx lanes)
#pragma unroll
        for (int i = 0; i < 4; i++) {
            float rm = -1e30f;
#pragma unroll
            for (int j = 0; j < 4; j++) {
                float v = s[i][j] * scale;
                if (k0 + (tx << 2) + j >= NTOK) v = -1e30f;
                s[i][j] = v;
                rm = fmaxf(rm, v);
            }
#pragma unroll
            for (int off = 8; off >= 1; off >>= 1)
                rm = fmaxf(rm, __shfl_xor_sync(0xffffffffu, rm, off));
            float mn = fmaxf(m_i[i], rm);
            float fi = __expf(m_i[i] - mn);
            m_i[i] = mn;
            float rs = 0.f;
#pragma unroll
            for (int j = 0; j < 4; j++) {
                float p = __expf(s[i][j] - mn);
                s[i][j] = p;
                rs += p;
            }
#pragma unroll
            for (int off = 8; off >= 1; off >>= 1)
                rs += __shfl_xor_sync(0xffffffffu, rs, off);
            l_i[i] = l_i[i] * fi + rs;
#pragma unroll
            for (int j = 0; j < 4; j++) o[i][j] *= fi;
        }

        __syncthreads();  // all K reads done; KP becomes P buffer

#pragma unroll
        for (int i = 0; i < 4; i++)
#pragma unroll
            for (int j = 0; j < 4; j++)
                KP[(ty << 2) + i][(tx << 2) + j] = s[i][j];

        __syncthreads();  // P visible

        // O += P @ V
#pragma unroll
        for (int c = 0; c < 64; c++) {
            float4 vv = *(const float4*)&Vs[c][tx << 2];
            float p0 = KP[(ty << 2) + 0][c];
            float p1 = KP[(ty << 2) + 1][c];
            float p2 = KP[(ty << 2) + 2][c];
            float p3 = KP[(ty << 2) + 3][c];
            o[0][0] = fmaf(p0, vv.x, o[0][0]); o[0][1] = fmaf(p0, vv.y, o[0][1]);
            o[0][2] = fmaf(p0, vv.z, o[0][2]); o[0][3] = fmaf(p0, vv.w, o[0][3]);
            o[1][0] = fmaf(p1, vv.x, o[1][0]); o[1][1] = fmaf(p1, vv.y, o[1][1]);
            o[1][2] = fmaf(p1, vv.z, o[1][2]); o[1][3] = fmaf(p1, vv.w, o[1][3]);
            o[2][0] = fmaf(p2, vv.x, o[2][0]); o[2][1] = fmaf(p2, vv.y, o[2][1]);
            o[2][2] = fmaf(p2, vv.z, o[2][2]); o[2][3] = fmaf(p2, vv.w, o[2][3]);
            o[3][0] = fmaf(p3, vv.x, o[3][0]); o[3][1] = fmaf(p3, vv.y, o[3][1]);
            o[3][2] = fmaf(p3, vv.z, o[3][2]); o[3][3] = fmaf(p3, vv.w, o[3][3]);
        }
    }

    // write (B, N, H*D) for the proj GEMM
    const int b = bh / HEADS;
    const int h = bh % HEADS;
#pragma unroll
    for (int i = 0; i < 4; i++) {
        int n = q0 + (ty << 2) + i;
        if (n < NTOK) {
            float inv = 1.f / l_i[i];
            float4 r;
            r.x = o[i][0] * inv;
            r.y = o[i][1] * inv;
            r.z = o[i][2] * inv;
            r.w = o[i][3] * inv;
            *(float4*)(g_attn + (size_t)(b * NTOK + n) * CDIM + h * DHEAD + (tx << 2)) = r;
        }
    }
}

// ================================ launch ====================================
extern "C" void kernel_launch(void* const* d_in, const int* in_sizes, int n_in,
                              void* d_out, int out_size) {
    const float* x      = (const float*)d_in[0];
    const float* cosb   = (const float*)d_in[1];
    const float* sinb   = (const float*)d_in[2];
    const float* w_qkv  = (const float*)d_in[3];
    const float* b_qkv  = (const float*)d_in[4];
    const float* w_proj = (const float*)d_in[5];
    const float* b_proj = (const float*)d_in[6];
    float* out = (float*)d_out;

    // 1) QKV GEMM
    {
        dim3 grid(QKVCOLS / 128, (MROWS + 127) / 128);
        k_gemm_qkv<<<grid, 256>>>(x, w_qkv, b_qkv);
    }
    // 2) RoPE + split/transpose
    {
        int total = BATCH * HEADS * NTOK * (DHEAD / 2);
        k_rope_split<<<(total + 255) / 256, 256>>>(cosb, sinb);
    }
    // 3) attention
    {
        dim3 grid((NTOK + 63) / 64, BHTOT);
        k_attn<<<grid, 256>>>();
    }
    // 4) output projection
    {
        dim3 grid(CDIM / 128, (MROWS + 127) / 128);
        k_gemm_proj<<<grid, 256>>>(w_proj, b_proj, out);
    }
}